// round 12
// baseline (speedup 1.0000x reference)
#include <cuda_runtime.h>
#include <cuda_fp16.h>
#include <cmath>
#include <cstdint>

#define S_LEN 2048
#define DH 64
#define BQ 128
#define PHROWS 256
#define NPH (S_LEN / PHROWS)    // 8 phases, 2 sub-tiles each
#define THREADS 512
#define KSTR 72                 // fp16 elems per padded row
#define ROWB (KSTR * 2)         // 144 bytes
#define PHB (PHROWS * ROWB)     // 36864 bytes (256 rows)

// smem: Qs @0 (18432), then 2 x (K phase buf + V phase buf)
#define OFF_Q  0
#define OFF_K0 18432
#define SMEM_TOTAL (18432 + 4 * PHB)   // 165888

#define NELEM (2 * 12 * 2048 * 64)
__device__ __align__(16) __half g_Kh[NELEM];
__device__ __align__(16) __half g_Vh[NELEM];

__device__ __forceinline__ uint32_t smem_u32(const void* p) {
    uint32_t a;
    asm("{ .reg .u64 t; cvta.to.shared.u64 t, %1; cvt.u32.u64 %0, t; }" : "=r"(a) : "l"(p));
    return a;
}
__device__ __forceinline__ uint32_t cvt2h(float lo, float hi) {
    uint32_t r;
    asm("cvt.rn.f16x2.f32 %0, %1, %2;" : "=r"(r) : "f"(hi), "f"(lo));
    return r;
}
__device__ __forceinline__ uint32_t h2ex2(uint32_t x) {
    uint32_t r;
    asm("ex2.approx.f16x2 %0, %1;" : "=r"(r) : "r"(x));
    return r;
}
__device__ __forceinline__ float2 h2f2(uint32_t v) {
    __half2 h = *reinterpret_cast<__half2*>(&v);
    return __half22float2(h);
}
__device__ __forceinline__ void ldsm_x4(uint32_t a, uint32_t* r) {
    asm volatile("ldmatrix.sync.aligned.m8n8.x4.shared.b16 {%0,%1,%2,%3}, [%4];"
                 : "=r"(r[0]), "=r"(r[1]), "=r"(r[2]), "=r"(r[3]) : "r"(a));
}
__device__ __forceinline__ void ldsm_x4_t(uint32_t a, uint32_t* r) {
    asm volatile("ldmatrix.sync.aligned.m8n8.x4.trans.shared.b16 {%0,%1,%2,%3}, [%4];"
                 : "=r"(r[0]), "=r"(r[1]), "=r"(r[2]), "=r"(r[3]) : "r"(a));
}
__device__ __forceinline__ void mma16816(float c[4], const uint32_t a[4],
                                         uint32_t b0, uint32_t b1) {
    asm volatile(
        "mma.sync.aligned.m16n8k16.row.col.f32.f16.f16.f32 "
        "{%0,%1,%2,%3}, {%4,%5,%6,%7}, {%8,%9}, {%0,%1,%2,%3};"
        : "+f"(c[0]), "+f"(c[1]), "+f"(c[2]), "+f"(c[3])
        : "r"(a[0]), "r"(a[1]), "r"(a[2]), "r"(a[3]), "r"(b0), "r"(b1));
}
#define CP16(s, g) asm volatile("cp.async.cg.shared.global [%0], [%1], 16;" :: "r"(s), "l"(g))
#define CP_COMMIT() asm volatile("cp.async.commit_group;" ::: "memory")
#define CP_WAIT0()  asm volatile("cp.async.wait_group 0;" ::: "memory")
#define BARH(id)    asm volatile("bar.sync %0, 256;" :: "r"(id) : "memory")

// ---- pre-kernel: K,V fp32 -> fp16 once ----
__global__ void __launch_bounds__(256)
cvt_kv_kernel(const float* __restrict__ K, const float* __restrict__ V)
{
    size_t i = ((size_t)blockIdx.x * 256 + threadIdx.x) * 4;
    float4 k = *(const float4*)(K + i);
    *(uint2*)&g_Kh[i] = make_uint2(cvt2h(k.x, k.y), cvt2h(k.z, k.w));
    float4 v = *(const float4*)(V + i);
    *(uint2*)&g_Vh[i] = make_uint2(cvt2h(v.x, v.y), cvt2h(v.z, v.w));
}

__global__ void __launch_bounds__(THREADS, 1)
sdpa_ph3_kernel(const float* __restrict__ Qg, float* __restrict__ Og, float qscale)
{
    extern __shared__ char sm[];
    const uint32_t sbase = smem_u32(sm);

    const int tid  = threadIdx.x;
    const int warp = tid >> 5;
    const int lane = tid & 31;
    const int g    = lane >> 2;
    const int tg   = lane & 3;
    const int half = warp >> 3;           // j half; warps 0-7 / 8-15
    const int R0   = (warp & 7) * 16;     // warp's 16 q rows
    const int J0   = half * 64;           // j offset within a 128-sub-tile

    const int bh = blockIdx.y;
    const int q0 = blockIdx.x * BQ;
    const size_t base = (size_t)bh * (size_t)S_LEN * DH;

    // per-HALF cp.async staging: this half loads exactly the rows it reads
    const int ltid = tid & 255;
    const int r6   = ltid >> 1;                               // 0..127
    const int brow = (r6 & 63) + J0 + (r6 >> 6) * 128;        // buffer row
    const int ch0  = (ltid & 1) * 4;                          // chunk group

    const __half* gK = g_Kh + base;
    const __half* gV = g_Vh + base;

    // ---- prologue: phase 0 -> buf 0 ----
    {
        const __half* kp = gK + (size_t)brow * DH;
        const __half* vp = gV + (size_t)brow * DH;
        uint32_t so = sbase + OFF_K0 + brow * ROWB;
        #pragma unroll
        for (int i = 0; i < 4; ++i) {
            int ch = ch0 + i;
            CP16(so + ch * 16, kp + ch * 8);
            CP16(so + PHB + ch * 16, vp + ch * 8);
        }
        CP_COMMIT();
    }

    // ---- stage Q (scaled) fp16, pull A-frags ----
    {
        __half* Qs = (__half*)(sm + OFF_Q);
        const float* Qp = Qg + base + (size_t)q0 * DH;
        const int lr = tid >> 4;
        const int lc = (tid & 15) << 2;
        #pragma unroll
        for (int i = 0; i < 4; ++i) {
            int r = lr + i * 32;
            float4 v = *(const float4*)(Qp + r * DH + lc);
            v.x *= qscale; v.y *= qscale; v.z *= qscale; v.w *= qscale;
            *(uint2*)&Qs[r * KSTR + lc] = make_uint2(cvt2h(v.x, v.y), cvt2h(v.z, v.w));
        }
    }
    __syncthreads();

    uint32_t qf[4][4];
    {
        const __half* Qs = (const __half*)(sm + OFF_Q);
        const int r = R0 + g;
        #pragma unroll
        for (int kb = 0; kb < 4; ++kb) {
            int d = kb * 16 + tg * 2;
            qf[kb][0] = *(const uint32_t*)&Qs[r * KSTR + d];
            qf[kb][1] = *(const uint32_t*)&Qs[(r + 8) * KSTR + d];
            qf[kb][2] = *(const uint32_t*)&Qs[r * KSTR + d + 8];
            qf[kb][3] = *(const uint32_t*)&Qs[(r + 8) * KSTR + d + 8];
        }
    }

    float oc[8][4];
    #pragma unroll
    for (int n = 0; n < 8; ++n)
        #pragma unroll
        for (int e = 0; e < 4; ++e) oc[n][e] = 0.0f;
    float rs0 = 0.0f, rs1 = 0.0f;

    const int krow_off = (lane & 7) + ((lane >> 4) << 3);
    const int kcol_off = ((lane >> 3) & 1) << 3;
    const int vrow_off = (lane & 7) + (((lane >> 3) & 1) << 3);
    const int vcol_off = (lane >> 4) << 3;

    for (int p = 0; p < NPH; ++p) {
        const uint32_t kbase = sbase + OFF_K0 + (p & 1) * 2 * PHB;
        const uint32_t vbase = kbase + PHB;

        CP_WAIT0();
        BARH(1 + half);       // only this half's 8 warps sync

        if (p + 1 < NPH) {
            const uint32_t kn = sbase + OFF_K0 + ((p + 1) & 1) * 2 * PHB;
            const __half* kp = gK + (size_t)((p + 1) * PHROWS + brow) * DH;
            const __half* vp = gV + (size_t)((p + 1) * PHROWS + brow) * DH;
            uint32_t so = kn + brow * ROWB;
            #pragma unroll
            for (int i = 0; i < 4; ++i) {
                int ch = ch0 + i;
                CP16(so + ch * 16, kp + ch * 8);
                CP16(so + PHB + ch * 16, vp + ch * 8);
            }
            CP_COMMIT();
        }

        #pragma unroll
        for (int s = 0; s < 2; ++s) {
            const uint32_t kbuf = kbase + s * 128 * ROWB;
            const uint32_t vbuf = vbase + s * 128 * ROWB;

            // ---- S = Q K^T : 16 rows x 64 cols ----
            float sc[8][4];
            #pragma unroll
            for (int n = 0; n < 8; ++n)
                #pragma unroll
                for (int e = 0; e < 4; ++e) sc[n][e] = 0.0f;

            #pragma unroll
            for (int jp = 0; jp < 4; ++jp) {
                uint32_t kf[4][4];
                const int row = J0 + jp * 16 + krow_off;
                #pragma unroll
                for (int kb = 0; kb < 4; ++kb)
                    ldsm_x4(kbuf + row * ROWB + (kb * 16 + kcol_off) * 2, kf[kb]);
                #pragma unroll
                for (int kb = 0; kb < 4; ++kb) {
                    mma16816(sc[2 * jp],     qf[kb], kf[kb][0], kf[kb][1]);
                    mma16816(sc[2 * jp + 1], qf[kb], kf[kb][2], kf[kb][3]);
                }
            }

            // ---- p = exp2(s) packed f16x2 -> P fragments ----
            // fragment rows: pa[kb][0], pa[kb][2] = row g ; pa[kb][1], pa[kb][3] = row g+8
            uint32_t pa[4][4];
            #pragma unroll
            for (int kb = 0; kb < 4; ++kb) {
                pa[kb][0] = h2ex2(cvt2h(sc[2 * kb][0],     sc[2 * kb][1]));
                pa[kb][1] = h2ex2(cvt2h(sc[2 * kb][2],     sc[2 * kb][3]));
                pa[kb][2] = h2ex2(cvt2h(sc[2 * kb + 1][0], sc[2 * kb + 1][1]));
                pa[kb][3] = h2ex2(cvt2h(sc[2 * kb + 1][2], sc[2 * kb + 1][3]));
            }

            // ---- rowsum in fp32 from the SAME fp16 p values ----
            // FIX vs r10/r11: row g = pa[kb][0] + pa[kb][2]; row g+8 = pa[kb][1] + pa[kb][3]
            #pragma unroll
            for (int kb = 0; kb < 4; ++kb) {
                float2 a0 = h2f2(pa[kb][0]);
                float2 a2 = h2f2(pa[kb][2]);
                rs0 += (a0.x + a0.y) + (a2.x + a2.y);
                float2 a1 = h2f2(pa[kb][1]);
                float2 a3 = h2f2(pa[kb][3]);
                rs1 += (a1.x + a1.y) + (a3.x + a3.y);
            }

            // ---- O += P V ----
            #pragma unroll
            for (int kb = 0; kb < 4; ++kb) {
                uint32_t vf[4][4];
                const int row = J0 + kb * 16 + vrow_off;
                #pragma unroll
                for (int dp = 0; dp < 4; ++dp)
                    ldsm_x4_t(vbuf + row * ROWB + (dp * 16 + vcol_off) * 2, vf[dp]);
                #pragma unroll
                for (int dp = 0; dp < 4; ++dp) {
                    mma16816(oc[2 * dp],     pa[kb], vf[dp][0], vf[dp][1]);
                    mma16816(oc[2 * dp + 1], pa[kb], vf[dp][2], vf[dp][3]);
                }
            }
        }
    }

    // ---- reduce rowsums over the 4 col-lanes ----
    rs0 += __shfl_xor_sync(0xffffffffu, rs0, 1);
    rs0 += __shfl_xor_sync(0xffffffffu, rs0, 2);
    rs1 += __shfl_xor_sync(0xffffffffu, rs1, 1);
    rs1 += __shfl_xor_sync(0xffffffffu, rs1, 2);

    __syncthreads();   // both halves done; reuse smem for combine

    float* OS = (float*)(sm + OFF_K0);   // 128 x 64 f32 partials (half 1)
    float* RS = (float*)(sm + OFF_Q);    // 128 rowsums (half 1)

    const int r = R0 + g;
    if (half == 1) {
        #pragma unroll
        for (int n = 0; n < 8; ++n) {
            int c = n * 8 + tg * 2;
            *(float2*)&OS[r * 64 + c]       = make_float2(oc[n][0], oc[n][1]);
            *(float2*)&OS[(r + 8) * 64 + c] = make_float2(oc[n][2], oc[n][3]);
        }
        if (tg == 0) { RS[r] = rs0; RS[r + 8] = rs1; }
    }
    __syncthreads();

    if (half == 0) {
        float invA = 1.0f / (rs0 + RS[r]);
        float invB = 1.0f / (rs1 + RS[r + 8]);
        float* OpA = Og + base + (size_t)(q0 + r) * DH;
        float* OpB = OpA + 8 * DH;
        #pragma unroll
        for (int n = 0; n < 8; ++n) {
            int c = n * 8 + tg * 2;
            float2 pA = *(const float2*)&OS[r * 64 + c];
            float2 pB = *(const float2*)&OS[(r + 8) * 64 + c];
            *(float2*)(OpA + c) = make_float2((oc[n][0] + pA.x) * invA,
                                              (oc[n][1] + pA.y) * invA);
            *(float2*)(OpB + c) = make_float2((oc[n][2] + pB.x) * invB,
                                              (oc[n][3] + pB.y) * invB);
        }
    }
}

extern "C" void kernel_launch(void* const* d_in, const int* in_sizes, int n_in,
                              void* d_out, int out_size)
{
    const float* Q = (const float*)d_in[0];
    const float* K = (const float*)d_in[1];
    const float* V = (const float*)d_in[2];
    float* O = (float*)d_out;

    cudaFuncSetAttribute(sdpa_ph3_kernel,
                         cudaFuncAttributeMaxDynamicSharedMemorySize, SMEM_TOTAL);

    cvt_kv_kernel<<<NELEM / (256 * 4), 256>>>(K, V);

    const float qscale = (1.0f / sqrtf((float)S_LEN)) * 1.4426950408889634f;
    dim3 grid(S_LEN / BQ, 2 * 12);
    sdpa_ph3_kernel<<<grid, THREADS, SMEM_TOTAL>>>(Q, O, qscale);
}

// round 13
// speedup vs baseline: 1.2743x; 1.2743x over previous
#include <cuda_runtime.h>
#include <cuda_fp16.h>
#include <cmath>
#include <cstdint>

#define S_LEN 2048
#define DH 64
#define BQ 128
#define BK 128
#define NT (S_LEN / BK)
#define THREADS 512
#define KSTR 72                 // fp16 elems per padded row
#define ROWB (KSTR * 2)         // 144 bytes
#define TILE_B (128 * ROWB)     // 18432 bytes

// smem layout (bytes): Qs @0, K0 @18432, V0, K1, V1
#define OFF_Q  0
#define OFF_K0 18432
#define SMEM_TOTAL (18432 * 5)

#define NELEM (2 * 12 * 2048 * 64)
__device__ __align__(16) __half g_Kh[NELEM];
__device__ __align__(16) __half g_Vh[NELEM];

__device__ __forceinline__ uint32_t smem_u32(const void* p) {
    uint32_t a;
    asm("{ .reg .u64 t; cvta.to.shared.u64 t, %1; cvt.u32.u64 %0, t; }" : "=r"(a) : "l"(p));
    return a;
}
__device__ __forceinline__ uint32_t cvt2h(float lo, float hi) {
    uint32_t r;
    asm("cvt.rn.f16x2.f32 %0, %1, %2;" : "=r"(r) : "f"(hi), "f"(lo));
    return r;
}
__device__ __forceinline__ uint32_t h2ex2(uint32_t x) {
    uint32_t r;
    asm("ex2.approx.f16x2 %0, %1;" : "=r"(r) : "r"(x));
    return r;
}
__device__ __forceinline__ float2 h2f2(uint32_t v) {
    __half2 h = *reinterpret_cast<__half2*>(&v);
    return __half22float2(h);
}
__device__ __forceinline__ void ldsm_x4(uint32_t a, uint32_t* r) {
    asm volatile("ldmatrix.sync.aligned.m8n8.x4.shared.b16 {%0,%1,%2,%3}, [%4];"
                 : "=r"(r[0]), "=r"(r[1]), "=r"(r[2]), "=r"(r[3]) : "r"(a));
}
__device__ __forceinline__ void ldsm_x4_t(uint32_t a, uint32_t* r) {
    asm volatile("ldmatrix.sync.aligned.m8n8.x4.trans.shared.b16 {%0,%1,%2,%3}, [%4];"
                 : "=r"(r[0]), "=r"(r[1]), "=r"(r[2]), "=r"(r[3]) : "r"(a));
}
__device__ __forceinline__ void mma16816(float c[4], const uint32_t a[4],
                                         uint32_t b0, uint32_t b1) {
    asm volatile(
        "mma.sync.aligned.m16n8k16.row.col.f32.f16.f16.f32 "
        "{%0,%1,%2,%3}, {%4,%5,%6,%7}, {%8,%9}, {%0,%1,%2,%3};"
        : "+f"(c[0]), "+f"(c[1]), "+f"(c[2]), "+f"(c[3])
        : "r"(a[0]), "r"(a[1]), "r"(a[2]), "r"(a[3]), "r"(b0), "r"(b1));
}
#define CP16(s, g) asm volatile("cp.async.cg.shared.global [%0], [%1], 16;" :: "r"(s), "l"(g))
#define CP_COMMIT() asm volatile("cp.async.commit_group;" ::: "memory")
#define CP_WAIT0()  asm volatile("cp.async.wait_group 0;" ::: "memory")
#define BARH(id)    asm volatile("bar.sync %0, 256;" :: "r"(id) : "memory")

// ---- pre-kernel: K,V fp32 -> fp16 once ----
__global__ void __launch_bounds__(256)
cvt_kv_kernel(const float* __restrict__ K, const float* __restrict__ V)
{
    size_t i = ((size_t)blockIdx.x * 256 + threadIdx.x) * 4;
    float4 k = *(const float4*)(K + i);
    *(uint2*)&g_Kh[i] = make_uint2(cvt2h(k.x, k.y), cvt2h(k.z, k.w));
    float4 v = *(const float4*)(V + i);
    *(uint2*)&g_Vh[i] = make_uint2(cvt2h(v.x, v.y), cvt2h(v.z, v.w));
}

__global__ void __launch_bounds__(THREADS, 1)
sdpa_r13_kernel(const float* __restrict__ Qg, float* __restrict__ Og, float qscale)
{
    extern __shared__ char sm[];
    const uint32_t sbase = smem_u32(sm);

    const int tid  = threadIdx.x;
    const int warp = tid >> 5;
    const int lane = tid & 31;
    const int g    = lane >> 2;
    const int tg   = lane & 3;
    const int half = warp >> 3;           // j half; warps 0-7 / 8-15
    const int R0   = (warp & 7) * 16;     // warp's 16 q rows
    const int J0   = half * 64;

    const int bh = blockIdx.y;
    const int q0 = blockIdx.x * BQ;
    const size_t base = (size_t)bh * (size_t)S_LEN * DH;

    // per-HALF coalesced cp.async staging: 8 threads cover one row's 128B
    const int ltid  = tid & 255;
    const int s_row = J0 + (ltid >> 3);   // rows s_row, s_row + 32
    const int c_col = (ltid & 7) * 8;
    const uint32_t c_so = (ltid & 7) * 16;

    const __half* gK = g_Kh + base;
    const __half* gV = g_Vh + base;

    // ---- prologue: tile 0 (own half rows) -> buf 0 ----
    #pragma unroll
    for (int i = 0; i < 2; ++i) {
        int r = s_row + i * 32;
        uint32_t so = r * ROWB + c_so;
        CP16(sbase + OFF_K0 + so, gK + r * DH + c_col);
        CP16(sbase + OFF_K0 + TILE_B + so, gV + r * DH + c_col);
    }
    CP_COMMIT();

    // ---- stage Q (scaled) fp16, pull A-frags ----
    {
        __half* Qs = (__half*)(sm + OFF_Q);
        const float* Qp = Qg + base + (size_t)q0 * DH;
        const int lr = tid >> 4;
        const int lc = (tid & 15) << 2;
        #pragma unroll
        for (int i = 0; i < 4; ++i) {
            int r = lr + i * 32;
            float4 v = *(const float4*)(Qp + r * DH + lc);
            v.x *= qscale; v.y *= qscale; v.z *= qscale; v.w *= qscale;
            *(uint2*)&Qs[r * KSTR + lc] = make_uint2(cvt2h(v.x, v.y), cvt2h(v.z, v.w));
        }
    }
    __syncthreads();

    uint32_t qf[4][4];
    {
        const __half* Qs = (const __half*)(sm + OFF_Q);
        const int r = R0 + g;
        #pragma unroll
        for (int kb = 0; kb < 4; ++kb) {
            int d = kb * 16 + tg * 2;
            qf[kb][0] = *(const uint32_t*)&Qs[r * KSTR + d];
            qf[kb][1] = *(const uint32_t*)&Qs[(r + 8) * KSTR + d];
            qf[kb][2] = *(const uint32_t*)&Qs[r * KSTR + d + 8];
            qf[kb][3] = *(const uint32_t*)&Qs[(r + 8) * KSTR + d + 8];
        }
    }

    float oc[8][4];
    #pragma unroll
    for (int n = 0; n < 8; ++n)
        #pragma unroll
        for (int e = 0; e < 4; ++e) oc[n][e] = 0.0f;
    float rs0 = 0.0f, rs1 = 0.0f;         // rows R0+g, R0+g+8

    const int krow_off = (lane & 7) + ((lane >> 4) << 3);
    const int kcol_off = ((lane >> 3) & 1) << 3;
    const int vrow_off = (lane & 7) + (((lane >> 3) & 1) << 3);
    const int vcol_off = (lane >> 4) << 3;

    for (int t = 0; t < NT; ++t) {
        const uint32_t kbuf = sbase + OFF_K0 + (t & 1) * 2 * TILE_B;
        const uint32_t vbuf = kbuf + TILE_B;

        CP_WAIT0();
        BARH(1 + half);       // sync only this half's 8 warps

        if (t + 1 < NT) {
            const uint32_t kn = sbase + OFF_K0 + ((t + 1) & 1) * 2 * TILE_B;
            const __half* kp = gK + (size_t)(t + 1) * BK * DH;
            const __half* vp = gV + (size_t)(t + 1) * BK * DH;
            #pragma unroll
            for (int i = 0; i < 2; ++i) {
                int r = s_row + i * 32;
                uint32_t so = r * ROWB + c_so;
                CP16(kn + so, kp + r * DH + c_col);
                CP16(kn + TILE_B + so, vp + r * DH + c_col);
            }
            CP_COMMIT();
        }

        // ---- S = Q K^T : 16 rows x 64 cols (this half) ----
        float sc[8][4];
        #pragma unroll
        for (int n = 0; n < 8; ++n)
            #pragma unroll
            for (int e = 0; e < 4; ++e) sc[n][e] = 0.0f;

        #pragma unroll
        for (int jp = 0; jp < 4; ++jp) {
            uint32_t kf[4][4];
            const int row = J0 + jp * 16 + krow_off;
            #pragma unroll
            for (int kb = 0; kb < 4; ++kb)
                ldsm_x4(kbuf + row * ROWB + (kb * 16 + kcol_off) * 2, kf[kb]);
            #pragma unroll
            for (int kb = 0; kb < 4; ++kb) {
                mma16816(sc[2 * jp],     qf[kb], kf[kb][0], kf[kb][1]);
                mma16816(sc[2 * jp + 1], qf[kb], kf[kb][2], kf[kb][3]);
            }
        }

        // ---- p = exp2(s) packed f16x2 -> P fragments ----
        // rows: pa[kb][0], pa[kb][2] = row g ; pa[kb][1], pa[kb][3] = row g+8
        uint32_t pa[4][4];
        #pragma unroll
        for (int kb = 0; kb < 4; ++kb) {
            pa[kb][0] = h2ex2(cvt2h(sc[2 * kb][0],     sc[2 * kb][1]));
            pa[kb][1] = h2ex2(cvt2h(sc[2 * kb][2],     sc[2 * kb][3]));
            pa[kb][2] = h2ex2(cvt2h(sc[2 * kb + 1][0], sc[2 * kb + 1][1]));
            pa[kb][3] = h2ex2(cvt2h(sc[2 * kb + 1][2], sc[2 * kb + 1][3]));
        }

        // ---- rowsum in fp32 from the SAME fp16 p values ----
        #pragma unroll
        for (int kb = 0; kb < 4; ++kb) {
            float2 a0 = h2f2(pa[kb][0]);
            float2 a2 = h2f2(pa[kb][2]);
            rs0 += (a0.x + a0.y) + (a2.x + a2.y);
            float2 a1 = h2f2(pa[kb][1]);
            float2 a3 = h2f2(pa[kb][3]);
            rs1 += (a1.x + a1.y) + (a3.x + a3.y);
        }

        // ---- O += P V (this j-half) ----
        #pragma unroll
        for (int kb = 0; kb < 4; ++kb) {
            uint32_t vf[4][4];
            const int row = J0 + kb * 16 + vrow_off;
            #pragma unroll
            for (int dp = 0; dp < 4; ++dp)
                ldsm_x4_t(vbuf + row * ROWB + (dp * 16 + vcol_off) * 2, vf[dp]);
            #pragma unroll
            for (int dp = 0; dp < 4; ++dp) {
                mma16816(oc[2 * dp],     pa[kb], vf[dp][0], vf[dp][1]);
                mma16816(oc[2 * dp + 1], pa[kb], vf[dp][2], vf[dp][3]);
            }
        }
    }

    // ---- reduce rowsums over the 4 col-lanes ----
    rs0 += __shfl_xor_sync(0xffffffffu, rs0, 1);
    rs0 += __shfl_xor_sync(0xffffffffu, rs0, 2);
    rs1 += __shfl_xor_sync(0xffffffffu, rs1, 1);
    rs1 += __shfl_xor_sync(0xffffffffu, rs1, 2);

    __syncthreads();   // both halves done; reuse smem for combine

    float* OS = (float*)(sm + OFF_K0);   // 128 x 64 f32 partials (half 1)
    float* RS = (float*)(sm + OFF_Q);    // 128 rowsums (half 1)

    const int r = R0 + g;
    if (half == 1) {
        #pragma unroll
        for (int n = 0; n < 8; ++n) {
            int c = n * 8 + tg * 2;
            *(float2*)&OS[r * 64 + c]       = make_float2(oc[n][0], oc[n][1]);
            *(float2*)&OS[(r + 8) * 64 + c] = make_float2(oc[n][2], oc[n][3]);
        }
        if (tg == 0) { RS[r] = rs0; RS[r + 8] = rs1; }
    }
    __syncthreads();

    if (half == 0) {
        float invA = 1.0f / (rs0 + RS[r]);
        float invB = 1.0f / (rs1 + RS[r + 8]);
        float* OpA = Og + base + (size_t)(q0 + r) * DH;
        float* OpB = OpA + 8 * DH;
        #pragma unroll
        for (int n = 0; n < 8; ++n) {
            int c = n * 8 + tg * 2;
            float2 pA = *(const float2*)&OS[r * 64 + c];
            float2 pB = *(const float2*)&OS[(r + 8) * 64 + c];
            *(float2*)(OpA + c) = make_float2((oc[n][0] + pA.x) * invA,
                                              (oc[n][1] + pA.y) * invA);
            *(float2*)(OpB + c) = make_float2((oc[n][2] + pB.x) * invB,
                                              (oc[n][3] + pB.y) * invB);
        }
    }
}

extern "C" void kernel_launch(void* const* d_in, const int* in_sizes, int n_in,
                              void* d_out, int out_size)
{
    const float* Q = (const float*)d_in[0];
    const float* K = (const float*)d_in[1];
    const float* V = (const float*)d_in[2];
    float* O = (float*)d_out;

    cudaFuncSetAttribute(sdpa_r13_kernel,
                         cudaFuncAttributeMaxDynamicSharedMemorySize, SMEM_TOTAL);

    cvt_kv_kernel<<<NELEM / (256 * 4), 256>>>(K, V);

    const float qscale = (1.0f / sqrtf((float)S_LEN)) * 1.4426950408889634f;
    dim3 grid(S_LEN / BQ, 2 * 12);
    sdpa_r13_kernel<<<grid, THREADS, SMEM_TOTAL>>>(Q, O, qscale);
}

// round 14
// speedup vs baseline: 1.3631x; 1.0697x over previous
#include <cuda_runtime.h>
#include <cuda_fp16.h>
#include <cmath>
#include <cstdint>

#define S_LEN 2048
#define DH 64
#define BQ 128
#define BK 128
#define NT (S_LEN / BK)
#define THREADS 512
#define KSTR 72                 // fp16 elems per padded row (cols 64..71 = pad)
#define ROWB (KSTR * 2)         // 144 bytes
#define TILE_B (128 * ROWB)     // 18432 bytes

// smem layout (bytes): Qs @0, K0 @18432, V0, K1, V1
#define OFF_Q  0
#define OFF_K0 18432
#define SMEM_TOTAL (18432 * 5)

#define NELEM (2 * 12 * 2048 * 64)
__device__ __align__(16) __half g_Kh[NELEM];
__device__ __align__(16) __half g_Vh[NELEM];

__device__ __forceinline__ uint32_t smem_u32(const void* p) {
    uint32_t a;
    asm("{ .reg .u64 t; cvta.to.shared.u64 t, %1; cvt.u32.u64 %0, t; }" : "=r"(a) : "l"(p));
    return a;
}
__device__ __forceinline__ uint32_t cvt2h(float lo, float hi) {
    uint32_t r;
    asm("cvt.rn.f16x2.f32 %0, %1, %2;" : "=r"(r) : "f"(hi), "f"(lo));
    return r;
}
// packed fp16x2 exp2
__device__ __forceinline__ uint32_t h2ex2(uint32_t x) {
    uint32_t r;
    asm("ex2.approx.f16x2 %0, %1;" : "=r"(r) : "r"(x));
    return r;
}
__device__ __forceinline__ void ldsm_x4(uint32_t a, uint32_t* r) {
    asm volatile("ldmatrix.sync.aligned.m8n8.x4.shared.b16 {%0,%1,%2,%3}, [%4];"
                 : "=r"(r[0]), "=r"(r[1]), "=r"(r[2]), "=r"(r[3]) : "r"(a));
}
__device__ __forceinline__ void ldsm_x4_t(uint32_t a, uint32_t* r) {
    asm volatile("ldmatrix.sync.aligned.m8n8.x4.trans.shared.b16 {%0,%1,%2,%3}, [%4];"
                 : "=r"(r[0]), "=r"(r[1]), "=r"(r[2]), "=r"(r[3]) : "r"(a));
}
__device__ __forceinline__ void ldsm_x2_t(uint32_t a, uint32_t& r0, uint32_t& r1) {
    asm volatile("ldmatrix.sync.aligned.m8n8.x2.trans.shared.b16 {%0,%1}, [%2];"
                 : "=r"(r0), "=r"(r1) : "r"(a));
}
// f32-accumulator HMMA (PV + rowsum)
__device__ __forceinline__ void mma16816(float c[4], const uint32_t a[4],
                                         uint32_t b0, uint32_t b1) {
    asm volatile(
        "mma.sync.aligned.m16n8k16.row.col.f32.f16.f16.f32 "
        "{%0,%1,%2,%3}, {%4,%5,%6,%7}, {%8,%9}, {%0,%1,%2,%3};"
        : "+f"(c[0]), "+f"(c[1]), "+f"(c[2]), "+f"(c[3])
        : "r"(a[0]), "r"(a[1]), "r"(a[2]), "r"(a[3]), "r"(b0), "r"(b1));
}
// f16-accumulator HMMA (QK): C layout == P A-fragment layout, zero repack
__device__ __forceinline__ void mma16816h(uint32_t c[2], const uint32_t a[4],
                                          uint32_t b0, uint32_t b1) {
    asm volatile(
        "mma.sync.aligned.m16n8k16.row.col.f16.f16.f16.f16 "
        "{%0,%1}, {%2,%3,%4,%5}, {%6,%7}, {%0,%1};"
        : "+r"(c[0]), "+r"(c[1])
        : "r"(a[0]), "r"(a[1]), "r"(a[2]), "r"(a[3]), "r"(b0), "r"(b1));
}
#define CP16(s, g) asm volatile("cp.async.cg.shared.global [%0], [%1], 16;" :: "r"(s), "l"(g))
#define CP_COMMIT() asm volatile("cp.async.commit_group;" ::: "memory")
#define CP_WAIT0()  asm volatile("cp.async.wait_group 0;" ::: "memory")
#define BARH(id)    asm volatile("bar.sync %0, 256;" :: "r"(id) : "memory")

// ---- pre-kernel: K,V fp32 -> fp16 once ----
__global__ void __launch_bounds__(256)
cvt_kv_kernel(const float* __restrict__ K, const float* __restrict__ V)
{
    size_t i = ((size_t)blockIdx.x * 256 + threadIdx.x) * 4;
    float4 k = *(const float4*)(K + i);
    *(uint2*)&g_Kh[i] = make_uint2(cvt2h(k.x, k.y), cvt2h(k.z, k.w));
    float4 v = *(const float4*)(V + i);
    *(uint2*)&g_Vh[i] = make_uint2(cvt2h(v.x, v.y), cvt2h(v.z, v.w));
}

__global__ void __launch_bounds__(THREADS, 1)
sdpa_r14_kernel(const float* __restrict__ Qg, float* __restrict__ Og, float qscale)
{
    extern __shared__ char sm[];
    const uint32_t sbase = smem_u32(sm);

    const int tid  = threadIdx.x;
    const int warp = tid >> 5;
    const int lane = tid & 31;
    const int g    = lane >> 2;
    const int tg   = lane & 3;
    const int half = warp >> 3;           // j half; warps 0-7 / 8-15
    const int R0   = (warp & 7) * 16;     // warp's 16 q rows
    const int J0   = half * 64;

    const int bh = blockIdx.y;
    const int q0 = blockIdx.x * BQ;
    const size_t base = (size_t)bh * (size_t)S_LEN * DH;

    // per-HALF coalesced cp.async staging: 8 threads cover one row's 128B
    const int ltid  = tid & 255;
    const int s_row = J0 + (ltid >> 3);   // rows s_row, s_row + 32
    const int c_col = (ltid & 7) * 8;
    const uint32_t c_so = (ltid & 7) * 16;

    const __half* gK = g_Kh + base;
    const __half* gV = g_Vh + base;

    // ---- prologue: tile 0 (own half rows) -> buf 0 ----
    #pragma unroll
    for (int i = 0; i < 2; ++i) {
        int r = s_row + i * 32;
        uint32_t so = r * ROWB + c_so;
        CP16(sbase + OFF_K0 + so, gK + r * DH + c_col);
        CP16(sbase + OFF_K0 + TILE_B + so, gV + r * DH + c_col);
    }
    CP_COMMIT();

    // ---- ones column for rowsum-via-MMA: V col 64 = 1.0, 65..71 = 0 (both bufs) ----
    if (tid < 256) {
        int row = tid & 127, b = tid >> 7;
        *(uint4*)(sm + OFF_K0 + b * 2 * TILE_B + TILE_B + row * ROWB + 128) =
            make_uint4(0x00003C00u, 0u, 0u, 0u);
    }

    // ---- stage Q (scaled) fp16, pull A-frags ----
    {
        __half* Qs = (__half*)(sm + OFF_Q);
        const float* Qp = Qg + base + (size_t)q0 * DH;
        const int lr = tid >> 4;
        const int lc = (tid & 15) << 2;
        #pragma unroll
        for (int i = 0; i < 4; ++i) {
            int r = lr + i * 32;
            float4 v = *(const float4*)(Qp + r * DH + lc);
            v.x *= qscale; v.y *= qscale; v.z *= qscale; v.w *= qscale;
            *(uint2*)&Qs[r * KSTR + lc] = make_uint2(cvt2h(v.x, v.y), cvt2h(v.z, v.w));
        }
    }
    __syncthreads();

    uint32_t qf[4][4];
    {
        const __half* Qs = (const __half*)(sm + OFF_Q);
        const int r = R0 + g;
        #pragma unroll
        for (int kb = 0; kb < 4; ++kb) {
            int d = kb * 16 + tg * 2;
            qf[kb][0] = *(const uint32_t*)&Qs[r * KSTR + d];
            qf[kb][1] = *(const uint32_t*)&Qs[(r + 8) * KSTR + d];
            qf[kb][2] = *(const uint32_t*)&Qs[r * KSTR + d + 8];
            qf[kb][3] = *(const uint32_t*)&Qs[(r + 8) * KSTR + d + 8];
        }
    }

    float oc[8][4];
    #pragma unroll
    for (int n = 0; n < 8; ++n)
        #pragma unroll
        for (int e = 0; e < 4; ++e) oc[n][e] = 0.0f;
    float oce[4] = {0.0f, 0.0f, 0.0f, 0.0f};   // ones-column accum (rowsum)

    const int krow_off = (lane & 7) + ((lane >> 4) << 3);
    const int kcol_off = ((lane >> 3) & 1) << 3;
    const int vrow_off = (lane & 7) + (((lane >> 3) & 1) << 3);
    const int vcol_off = (lane >> 4) << 3;

    for (int t = 0; t < NT; ++t) {
        const uint32_t kbuf = sbase + OFF_K0 + (t & 1) * 2 * TILE_B;
        const uint32_t vbuf = kbuf + TILE_B;

        CP_WAIT0();
        BARH(1 + half);       // sync only this half's 8 warps; halves drift freely

        if (t + 1 < NT) {
            const uint32_t kn = sbase + OFF_K0 + ((t + 1) & 1) * 2 * TILE_B;
            const __half* kp = gK + (size_t)(t + 1) * BK * DH;
            const __half* vp = gV + (size_t)(t + 1) * BK * DH;
            #pragma unroll
            for (int i = 0; i < 2; ++i) {
                int r = s_row + i * 32;
                uint32_t so = r * ROWB + c_so;
                CP16(kn + so, kp + r * DH + c_col);
                CP16(kn + TILE_B + so, vp + r * DH + c_col);
            }
            CP_COMMIT();
        }

        // ---- S = Q K^T : f16 accumulators (layout == P A-frag layout) ----
        uint32_t sch[8][2];
        #pragma unroll
        for (int n = 0; n < 8; ++n) { sch[n][0] = 0u; sch[n][1] = 0u; }

        #pragma unroll
        for (int jp = 0; jp < 4; ++jp) {
            uint32_t kf[4][4];
            const int row = J0 + jp * 16 + krow_off;
            #pragma unroll
            for (int kb = 0; kb < 4; ++kb)
                ldsm_x4(kbuf + row * ROWB + (kb * 16 + kcol_off) * 2, kf[kb]);
            #pragma unroll
            for (int kb = 0; kb < 4; ++kb) {
                mma16816h(sch[2 * jp],     qf[kb], kf[kb][0], kf[kb][1]);
                mma16816h(sch[2 * jp + 1], qf[kb], kf[kb][2], kf[kb][3]);
            }
        }

        // ---- p = exp2(s): direct on packed f16 accumulators, zero repack ----
        uint32_t pa[4][4];
        #pragma unroll
        for (int kb = 0; kb < 4; ++kb) {
            pa[kb][0] = h2ex2(sch[2 * kb][0]);
            pa[kb][1] = h2ex2(sch[2 * kb][1]);
            pa[kb][2] = h2ex2(sch[2 * kb + 1][0]);
            pa[kb][3] = h2ex2(sch[2 * kb + 1][1]);
        }

        // ---- O += P V ; rowsum via ones column (col 64) ----
        #pragma unroll
        for (int kb = 0; kb < 4; ++kb) {
            uint32_t vf[4][4];
            const int row = J0 + kb * 16 + vrow_off;
            #pragma unroll
            for (int dp = 0; dp < 4; ++dp)
                ldsm_x4_t(vbuf + row * ROWB + (dp * 16 + vcol_off) * 2, vf[dp]);
            uint32_t e0, e1;
            ldsm_x2_t(vbuf + row * ROWB + 128, e0, e1);
            #pragma unroll
            for (int dp = 0; dp < 4; ++dp) {
                mma16816(oc[2 * dp],     pa[kb], vf[dp][0], vf[dp][1]);
                mma16816(oc[2 * dp + 1], pa[kb], vf[dp][2], vf[dp][3]);
            }
            mma16816(oce, pa[kb], e0, e1);
        }
    }

    // rowsum lives in ones-block col 0 (tg==0 lanes): rows R0+g, R0+g+8
    float rs0 = __shfl_sync(0xffffffffu, oce[0], lane & 28);
    float rs1 = __shfl_sync(0xffffffffu, oce[2], lane & 28);

    __syncthreads();   // both halves done; reuse smem for combine

    float* OS = (float*)(sm + OFF_K0);   // 128 x 64 f32 partials (half 1)
    float* RS = (float*)(sm + OFF_Q);    // 128 rowsums (half 1)

    const int r = R0 + g;
    if (half == 1) {
        #pragma unroll
        for (int n = 0; n < 8; ++n) {
            int c = n * 8 + tg * 2;
            *(float2*)&OS[r * 64 + c]       = make_float2(oc[n][0], oc[n][1]);
            *(float2*)&OS[(r + 8) * 64 + c] = make_float2(oc[n][2], oc[n][3]);
        }
        if (tg == 0) { RS[r] = rs0; RS[r + 8] = rs1; }
    }
    __syncthreads();

    if (half == 0) {
        float invA = 1.0f / (rs0 + RS[r]);
        float invB = 1.0f / (rs1 + RS[r + 8]);
        float* OpA = Og + base + (size_t)(q0 + r) * DH;
        float* OpB = OpA + 8 * DH;
        #pragma unroll
        for (int n = 0; n < 8; ++n) {
            int c = n * 8 + tg * 2;
            float2 pA = *(const float2*)&OS[r * 64 + c];
            float2 pB = *(const float2*)&OS[(r + 8) * 64 + c];
            *(float2*)(OpA + c) = make_float2((oc[n][0] + pA.x) * invA,
                                              (oc[n][1] + pA.y) * invA);
            *(float2*)(OpB + c) = make_float2((oc[n][2] + pB.x) * invB,
                                              (oc[n][3] + pB.y) * invB);
        }
    }
}

extern "C" void kernel_launch(void* const* d_in, const int* in_sizes, int n_in,
                              void* d_out, int out_size)
{
    const float* Q = (const float*)d_in[0];
    const float* K = (const float*)d_in[1];
    const float* V = (const float*)d_in[2];
    float* O = (float*)d_out;

    cudaFuncSetAttribute(sdpa_r14_kernel,
                         cudaFuncAttributeMaxDynamicSharedMemorySize, SMEM_TOTAL);

    cvt_kv_kernel<<<NELEM / (256 * 4), 256>>>(K, V);

    const float qscale = (1.0f / sqrtf((float)S_LEN)) * 1.4426950408889634f;
    dim3 grid(S_LEN / BQ, 2 * 12);
    sdpa_r14_kernel<<<grid, THREADS, SMEM_TOTAL>>>(Q, O, qscale);
}

// round 15
// speedup vs baseline: 1.3636x; 1.0004x over previous
#include <cuda_runtime.h>
#include <cuda_fp16.h>
#include <cmath>
#include <cstdint>

#define S_LEN 2048
#define DH 64
#define BQ 128
#define BK 128
#define NT (S_LEN / BK)
#define THREADS 256
#define KSTR 72                 // fp16 elems per padded row (cols 64..71 = pad)
#define ROWB (KSTR * 2)         // 144 bytes
#define TILE_B (128 * ROWB)     // 18432 bytes

// smem layout (bytes): Qs @0, K0 @18432, V0, K1, V1
#define OFF_Q  0
#define OFF_K0 18432
#define SMEM_TOTAL (18432 * 5)

#define NELEM (2 * 12 * 2048 * 64)
__device__ __align__(16) __half g_Kh[NELEM];
__device__ __align__(16) __half g_Vh[NELEM];

__device__ __forceinline__ uint32_t smem_u32(const void* p) {
    uint32_t a;
    asm("{ .reg .u64 t; cvta.to.shared.u64 t, %1; cvt.u32.u64 %0, t; }" : "=r"(a) : "l"(p));
    return a;
}
__device__ __forceinline__ uint32_t cvt2h(float lo, float hi) {
    uint32_t r;
    asm("cvt.rn.f16x2.f32 %0, %1, %2;" : "=r"(r) : "f"(hi), "f"(lo));
    return r;
}
__device__ __forceinline__ uint32_t h2ex2(uint32_t x) {
    uint32_t r;
    asm("ex2.approx.f16x2 %0, %1;" : "=r"(r) : "r"(x));
    return r;
}
__device__ __forceinline__ void ldsm_x4(uint32_t a, uint32_t* r) {
    asm volatile("ldmatrix.sync.aligned.m8n8.x4.shared.b16 {%0,%1,%2,%3}, [%4];"
                 : "=r"(r[0]), "=r"(r[1]), "=r"(r[2]), "=r"(r[3]) : "r"(a));
}
__device__ __forceinline__ void ldsm_x4_t(uint32_t a, uint32_t* r) {
    asm volatile("ldmatrix.sync.aligned.m8n8.x4.trans.shared.b16 {%0,%1,%2,%3}, [%4];"
                 : "=r"(r[0]), "=r"(r[1]), "=r"(r[2]), "=r"(r[3]) : "r"(a));
}
__device__ __forceinline__ void ldsm_x2_t(uint32_t a, uint32_t& r0, uint32_t& r1) {
    asm volatile("ldmatrix.sync.aligned.m8n8.x2.trans.shared.b16 {%0,%1}, [%2];"
                 : "=r"(r0), "=r"(r1) : "r"(a));
}
// f32-accumulator HMMA (PV + rowsum)
__device__ __forceinline__ void mma16816(float c[4], const uint32_t a[4],
                                         uint32_t b0, uint32_t b1) {
    asm volatile(
        "mma.sync.aligned.m16n8k16.row.col.f32.f16.f16.f32 "
        "{%0,%1,%2,%3}, {%4,%5,%6,%7}, {%8,%9}, {%0,%1,%2,%3};"
        : "+f"(c[0]), "+f"(c[1]), "+f"(c[2]), "+f"(c[3])
        : "r"(a[0]), "r"(a[1]), "r"(a[2]), "r"(a[3]), "r"(b0), "r"(b1));
}
// f16-accumulator HMMA (QK): C layout == P A-fragment layout, zero repack
__device__ __forceinline__ void mma16816h(uint32_t c[2], const uint32_t a[4],
                                          uint32_t b0, uint32_t b1) {
    asm volatile(
        "mma.sync.aligned.m16n8k16.row.col.f16.f16.f16.f16 "
        "{%0,%1}, {%2,%3,%4,%5}, {%6,%7}, {%0,%1};"
        : "+r"(c[0]), "+r"(c[1])
        : "r"(a[0]), "r"(a[1]), "r"(a[2]), "r"(a[3]), "r"(b0), "r"(b1));
}
#define CP16(s, g) asm volatile("cp.async.cg.shared.global [%0], [%1], 16;" :: "r"(s), "l"(g))
#define CP_COMMIT() asm volatile("cp.async.commit_group;" ::: "memory")
#define CP_WAIT0()  asm volatile("cp.async.wait_group 0;" ::: "memory")
#define BARH(id)    asm volatile("bar.sync %0, 128;" :: "r"(id) : "memory")

// ---- pre-kernel: K,V fp32 -> fp16 once ----
__global__ void __launch_bounds__(256)
cvt_kv_kernel(const float* __restrict__ K, const float* __restrict__ V)
{
    size_t i = ((size_t)blockIdx.x * 256 + threadIdx.x) * 4;
    float4 k = *(const float4*)(K + i);
    *(uint2*)&g_Kh[i] = make_uint2(cvt2h(k.x, k.y), cvt2h(k.z, k.w));
    float4 v = *(const float4*)(V + i);
    *(uint2*)&g_Vh[i] = make_uint2(cvt2h(v.x, v.y), cvt2h(v.z, v.w));
}

__global__ void __launch_bounds__(THREADS, 1)
sdpa_r15_kernel(const float* __restrict__ Qg, float* __restrict__ Og, float qscale)
{
    extern __shared__ char sm[];
    const uint32_t sbase = smem_u32(sm);

    const int tid  = threadIdx.x;
    const int warp = tid >> 5;
    const int lane = tid & 31;
    const int g    = lane >> 2;
    const int half = warp >> 2;           // j half; warps 0-3 / 4-7
    const int R0   = (warp & 3) * 32;     // warp's 32 q rows
    const int J0   = half * 64;

    const int bh = blockIdx.y;
    const int q0 = blockIdx.x * BQ;
    const size_t base = (size_t)bh * (size_t)S_LEN * DH;

    // per-HALF coalesced cp.async staging: 8 threads cover one row's 128B
    const int ltid  = tid & 127;
    const int s_row = J0 + (ltid >> 3);   // rows s_row + i*16, i<4
    const int c_col = (ltid & 7) * 8;
    const uint32_t c_so = (ltid & 7) * 16;

    const __half* gK = g_Kh + base;
    const __half* gV = g_Vh + base;

    // ---- prologue: tile 0 (own half rows) -> buf 0 ----
    #pragma unroll
    for (int i = 0; i < 4; ++i) {
        int r = s_row + i * 16;
        uint32_t so = r * ROWB + c_so;
        CP16(sbase + OFF_K0 + so, gK + r * DH + c_col);
        CP16(sbase + OFF_K0 + TILE_B + so, gV + r * DH + c_col);
    }
    CP_COMMIT();

    // ---- ones column for rowsum-via-MMA: V col 64 = 1.0, 65..71 = 0 (both bufs) ----
    {
        int row = tid & 127, b = tid >> 7;
        *(uint4*)(sm + OFF_K0 + b * 2 * TILE_B + TILE_B + row * ROWB + 128) =
            make_uint4(0x00003C00u, 0u, 0u, 0u);
    }

    // ---- stage Q (scaled) fp16, pull A-frags ----
    {
        __half* Qs = (__half*)(sm + OFF_Q);
        const float* Qp = Qg + base + (size_t)q0 * DH;
        const int lr = tid >> 4;          // 0..15
        const int lc = (tid & 15) << 2;
        #pragma unroll
        for (int i = 0; i < 8; ++i) {
            int r = lr + i * 16;
            float4 v = *(const float4*)(Qp + r * DH + lc);
            v.x *= qscale; v.y *= qscale; v.z *= qscale; v.w *= qscale;
            *(uint2*)&Qs[r * KSTR + lc] = make_uint2(cvt2h(v.x, v.y), cvt2h(v.z, v.w));
        }
    }
    __syncthreads();

    uint32_t qf[2][4][4];
    {
        const __half* Qs = (const __half*)(sm + OFF_Q);
        const int tg = lane & 3;
        #pragma unroll
        for (int mb = 0; mb < 2; ++mb) {
            const int r = R0 + mb * 16 + g;
            #pragma unroll
            for (int kb = 0; kb < 4; ++kb) {
                int d = kb * 16 + tg * 2;
                qf[mb][kb][0] = *(const uint32_t*)&Qs[r * KSTR + d];
                qf[mb][kb][1] = *(const uint32_t*)&Qs[(r + 8) * KSTR + d];
                qf[mb][kb][2] = *(const uint32_t*)&Qs[r * KSTR + d + 8];
                qf[mb][kb][3] = *(const uint32_t*)&Qs[(r + 8) * KSTR + d + 8];
            }
        }
    }

    float oc[2][8][4];
    #pragma unroll
    for (int mb = 0; mb < 2; ++mb)
        #pragma unroll
        for (int n = 0; n < 8; ++n)
            #pragma unroll
            for (int e = 0; e < 4; ++e) oc[mb][n][e] = 0.0f;
    float oce[2][4];
    #pragma unroll
    for (int mb = 0; mb < 2; ++mb)
        #pragma unroll
        for (int e = 0; e < 4; ++e) oce[mb][e] = 0.0f;

    const int krow_off = (lane & 7) + ((lane >> 4) << 3);
    const int kcol_off = ((lane >> 3) & 1) << 3;
    const int vrow_off = (lane & 7) + (((lane >> 3) & 1) << 3);
    const int vcol_off = (lane >> 4) << 3;

    for (int t = 0; t < NT; ++t) {
        const uint32_t kbuf = sbase + OFF_K0 + (t & 1) * 2 * TILE_B;
        const uint32_t vbuf = kbuf + TILE_B;

        CP_WAIT0();
        BARH(1 + half);       // sync only this half's 4 warps; halves drift freely

        if (t + 1 < NT) {
            const uint32_t kn = sbase + OFF_K0 + ((t + 1) & 1) * 2 * TILE_B;
            const __half* kp = gK + (size_t)(t + 1) * BK * DH;
            const __half* vp = gV + (size_t)(t + 1) * BK * DH;
            #pragma unroll
            for (int i = 0; i < 4; ++i) {
                int r = s_row + i * 16;
                uint32_t so = r * ROWB + c_so;
                CP16(kn + so, kp + r * DH + c_col);
                CP16(kn + TILE_B + so, vp + r * DH + c_col);
            }
            CP_COMMIT();
        }

        // ---- S = Q K^T : 32 rows x 64 cols, f16 accumulators ----
        uint32_t sch[2][8][2];
        #pragma unroll
        for (int mb = 0; mb < 2; ++mb)
            #pragma unroll
            for (int n = 0; n < 8; ++n) { sch[mb][n][0] = 0u; sch[mb][n][1] = 0u; }

        #pragma unroll
        for (int jp = 0; jp < 4; ++jp) {
            uint32_t kf[4][4];
            const int row = J0 + jp * 16 + krow_off;
            #pragma unroll
            for (int kb = 0; kb < 4; ++kb)
                ldsm_x4(kbuf + row * ROWB + (kb * 16 + kcol_off) * 2, kf[kb]);
            #pragma unroll
            for (int kb = 0; kb < 4; ++kb) {
                #pragma unroll
                for (int mb = 0; mb < 2; ++mb) {
                    mma16816h(sch[mb][2 * jp],     qf[mb][kb], kf[kb][0], kf[kb][1]);
                    mma16816h(sch[mb][2 * jp + 1], qf[mb][kb], kf[kb][2], kf[kb][3]);
                }
            }
        }

        // ---- p = exp2(s): direct on packed f16 accumulators ----
        uint32_t pa[2][4][4];
        #pragma unroll
        for (int mb = 0; mb < 2; ++mb)
            #pragma unroll
            for (int kb = 0; kb < 4; ++kb) {
                pa[mb][kb][0] = h2ex2(sch[mb][2 * kb][0]);
                pa[mb][kb][1] = h2ex2(sch[mb][2 * kb][1]);
                pa[mb][kb][2] = h2ex2(sch[mb][2 * kb + 1][0]);
                pa[mb][kb][3] = h2ex2(sch[mb][2 * kb + 1][1]);
            }

        // ---- O += P V ; rowsum via ones column (col 64) ----
        #pragma unroll
        for (int kb = 0; kb < 4; ++kb) {
            uint32_t vf[4][4];
            const int row = J0 + kb * 16 + vrow_off;
            #pragma unroll
            for (int dp = 0; dp < 4; ++dp)
                ldsm_x4_t(vbuf + row * ROWB + (dp * 16 + vcol_off) * 2, vf[dp]);
            uint32_t e0, e1;
            ldsm_x2_t(vbuf + row * ROWB + 128, e0, e1);
            #pragma unroll
            for (int dp = 0; dp < 4; ++dp) {
                #pragma unroll
                for (int mb = 0; mb < 2; ++mb) {
                    mma16816(oc[mb][2 * dp],     pa[mb][kb], vf[dp][0], vf[dp][1]);
                    mma16816(oc[mb][2 * dp + 1], pa[mb][kb], vf[dp][2], vf[dp][3]);
                }
            }
            #pragma unroll
            for (int mb = 0; mb < 2; ++mb)
                mma16816(oce[mb], pa[mb][kb], e0, e1);
        }
    }

    // rowsums: ones-block col 0 (tg==0 lanes): rows R0+16mb+g, +8
    float rsA[2], rsB[2];
    #pragma unroll
    for (int mb = 0; mb < 2; ++mb) {
        rsA[mb] = __shfl_sync(0xffffffffu, oce[mb][0], lane & 28);
        rsB[mb] = __shfl_sync(0xffffffffu, oce[mb][2], lane & 28);
    }

    __syncthreads();   // both halves done; reuse smem for combine

    float* OS = (float*)(sm + OFF_K0);   // 128 x 64 f32 partials (half 1)
    float* RS = (float*)(sm + OFF_Q);    // 128 rowsums (half 1)
    const int tg = lane & 3;

    if (half == 1) {
        #pragma unroll
        for (int mb = 0; mb < 2; ++mb) {
            const int r = R0 + mb * 16 + g;
            #pragma unroll
            for (int n = 0; n < 8; ++n) {
                int c = n * 8 + tg * 2;
                *(float2*)&OS[r * 64 + c]       = make_float2(oc[mb][n][0], oc[mb][n][1]);
                *(float2*)&OS[(r + 8) * 64 + c] = make_float2(oc[mb][n][2], oc[mb][n][3]);
            }
            if (tg == 0) { RS[r] = rsA[mb]; RS[r + 8] = rsB[mb]; }
        }
    }
    __syncthreads();

    if (half == 0) {
        #pragma unroll
        for (int mb = 0; mb < 2; ++mb) {
            const int r = R0 + mb * 16 + g;
            float invA = 1.0f / (rsA[mb] + RS[r]);
            float invB = 1.0f / (rsB[mb] + RS[r + 8]);
            float* OpA = Og + base + (size_t)(q0 + r) * DH;
            float* OpB = OpA + 8 * DH;
            #pragma unroll
            for (int n = 0; n < 8; ++n) {
                int c = n * 8 + tg * 2;
                float2 pA = *(const float2*)&OS[r * 64 + c];
                float2 pB = *(const float2*)&OS[(r + 8) * 64 + c];
                *(float2*)(OpA + c) = make_float2((oc[mb][n][0] + pA.x) * invA,
                                                  (oc[mb][n][1] + pA.y) * invA);
                *(float2*)(OpB + c) = make_float2((oc[mb][n][2] + pB.x) * invB,
                                                  (oc[mb][n][3] + pB.y) * invB);
            }
        }
    }
}

extern "C" void kernel_launch(void* const* d_in, const int* in_sizes, int n_in,
                              void* d_out, int out_size)
{
    const float* Q = (const float*)d_in[0];
    const float* K = (const float*)d_in[1];
    const float* V = (const float*)d_in[2];
    float* O = (float*)d_out;

    cudaFuncSetAttribute(sdpa_r15_kernel,
                         cudaFuncAttributeMaxDynamicSharedMemorySize, SMEM_TOTAL);

    cvt_kv_kernel<<<NELEM / (256 * 4), 256>>>(K, V);

    const float qscale = (1.0f / sqrtf((float)S_LEN)) * 1.4426950408889634f;
    dim3 grid(S_LEN / BQ, 2 * 12);
    sdpa_r15_kernel<<<grid, THREADS, SMEM_TOTAL>>>(Q, O, qscale);
}

// round 16
// speedup vs baseline: 1.3756x; 1.0088x over previous
#include <cuda_runtime.h>
#include <cuda_fp16.h>
#include <cmath>
#include <cstdint>

#define S_LEN 2048
#define DH 64
#define BQ 128
#define BK 128
#define NT (S_LEN / BK)
#define THREADS 256
#define KSTR 72                 // fp16 elems per padded row (cols 64..71 = pad)
#define ROWB (KSTR * 2)         // 144 bytes
#define TILE_B (128 * ROWB)     // 18432 bytes

// smem layout (bytes): Qs @0, K0 @18432, V0, K1, V1
#define OFF_Q  0
#define OFF_K0 18432
#define SMEM_TOTAL (18432 * 5)

#define NELEM (2 * 12 * 2048 * 64)
__device__ __align__(16) __half g_Kh[NELEM];
__device__ __align__(16) __half g_Vh[NELEM];

__device__ __forceinline__ uint32_t smem_u32(const void* p) {
    uint32_t a;
    asm("{ .reg .u64 t; cvta.to.shared.u64 t, %1; cvt.u32.u64 %0, t; }" : "=r"(a) : "l"(p));
    return a;
}
__device__ __forceinline__ uint32_t cvt2h(float lo, float hi) {
    uint32_t r;
    asm("cvt.rn.f16x2.f32 %0, %1, %2;" : "=r"(r) : "f"(hi), "f"(lo));
    return r;
}
__device__ __forceinline__ uint32_t h2ex2(uint32_t x) {
    uint32_t r;
    asm("ex2.approx.f16x2 %0, %1;" : "=r"(r) : "r"(x));
    return r;
}
__device__ __forceinline__ void ldsm_x4(uint32_t a, uint32_t* r) {
    asm volatile("ldmatrix.sync.aligned.m8n8.x4.shared.b16 {%0,%1,%2,%3}, [%4];"
                 : "=r"(r[0]), "=r"(r[1]), "=r"(r[2]), "=r"(r[3]) : "r"(a));
}
__device__ __forceinline__ void ldsm_x4_t(uint32_t a, uint32_t* r) {
    asm volatile("ldmatrix.sync.aligned.m8n8.x4.trans.shared.b16 {%0,%1,%2,%3}, [%4];"
                 : "=r"(r[0]), "=r"(r[1]), "=r"(r[2]), "=r"(r[3]) : "r"(a));
}
__device__ __forceinline__ void ldsm_x2_t(uint32_t a, uint32_t& r0, uint32_t& r1) {
    asm volatile("ldmatrix.sync.aligned.m8n8.x2.trans.shared.b16 {%0,%1}, [%2];"
                 : "=r"(r0), "=r"(r1) : "r"(a));
}
// f32-accumulator HMMA (PV + rowsum)
__device__ __forceinline__ void mma16816(float c[4], const uint32_t a[4],
                                         uint32_t b0, uint32_t b1) {
    asm volatile(
        "mma.sync.aligned.m16n8k16.row.col.f32.f16.f16.f32 "
        "{%0,%1,%2,%3}, {%4,%5,%6,%7}, {%8,%9}, {%0,%1,%2,%3};"
        : "+f"(c[0]), "+f"(c[1]), "+f"(c[2]), "+f"(c[3])
        : "r"(a[0]), "r"(a[1]), "r"(a[2]), "r"(a[3]), "r"(b0), "r"(b1));
}
// f16-accumulator HMMA (QK): C layout == P A-fragment layout, zero repack
__device__ __forceinline__ void mma16816h(uint32_t c[2], const uint32_t a[4],
                                          uint32_t b0, uint32_t b1) {
    asm volatile(
        "mma.sync.aligned.m16n8k16.row.col.f16.f16.f16.f16 "
        "{%0,%1}, {%2,%3,%4,%5}, {%6,%7}, {%0,%1};"
        : "+r"(c[0]), "+r"(c[1])
        : "r"(a[0]), "r"(a[1]), "r"(a[2]), "r"(a[3]), "r"(b0), "r"(b1));
}
#define CP16(s, g) asm volatile("cp.async.cg.shared.global [%0], [%1], 16;" :: "r"(s), "l"(g))
#define CP_COMMIT() asm volatile("cp.async.commit_group;" ::: "memory")
#define CP_WAIT0()  asm volatile("cp.async.wait_group 0;" ::: "memory")
#define BARH(id)    asm volatile("bar.sync %0, 128;" :: "r"(id) : "memory")

// ---- pre-kernel: K,V fp32 -> fp16 once ----
__global__ void __launch_bounds__(256)
cvt_kv_kernel(const float* __restrict__ K, const float* __restrict__ V)
{
    size_t i = ((size_t)blockIdx.x * 256 + threadIdx.x) * 4;
    float4 k = *(const float4*)(K + i);
    *(uint2*)&g_Kh[i] = make_uint2(cvt2h(k.x, k.y), cvt2h(k.z, k.w));
    float4 v = *(const float4*)(V + i);
    *(uint2*)&g_Vh[i] = make_uint2(cvt2h(v.x, v.y), cvt2h(v.z, v.w));
}

__global__ void __launch_bounds__(THREADS, 1)
sdpa_r16_kernel(const float* __restrict__ Qg, float* __restrict__ Og, float qscale)
{
    extern __shared__ char sm[];
    const uint32_t sbase = smem_u32(sm);

    const int tid  = threadIdx.x;
    const int warp = tid >> 5;
    const int lane = tid & 31;
    const int g    = lane >> 2;
    const int half = warp >> 2;           // j half; warps 0-3 / 4-7
    const int R0   = (warp & 3) * 32;     // warp's 32 q rows
    const int J0   = half * 64;

    const int bh = blockIdx.y;
    const int q0 = blockIdx.x * BQ;
    const size_t base = (size_t)bh * (size_t)S_LEN * DH;

    // per-HALF coalesced cp.async staging: 8 threads cover one row's 128B
    const int ltid  = tid & 127;
    const int s_row = J0 + (ltid >> 3);   // rows s_row + i*16, i<4
    const int c_col = (ltid & 7) * 8;
    const uint32_t c_so = (ltid & 7) * 16;

    const __half* gK = g_Kh + base;
    const __half* gV = g_Vh + base;

    // ---- prologue: tile 0 (own half rows) -> buf 0 ----
    #pragma unroll
    for (int i = 0; i < 4; ++i) {
        int r = s_row + i * 16;
        uint32_t so = r * ROWB + c_so;
        CP16(sbase + OFF_K0 + so, gK + r * DH + c_col);
        CP16(sbase + OFF_K0 + TILE_B + so, gV + r * DH + c_col);
    }
    CP_COMMIT();

    // ---- ones column for rowsum-via-MMA: V col 64 = 1.0, 65..71 = 0 (both bufs) ----
    {
        int row = tid & 127, b = tid >> 7;
        *(uint4*)(sm + OFF_K0 + b * 2 * TILE_B + TILE_B + row * ROWB + 128) =
            make_uint4(0x00003C00u, 0u, 0u, 0u);
    }

    // ---- stage Q (scaled) fp16, pull A-frags ----
    {
        __half* Qs = (__half*)(sm + OFF_Q);
        const float* Qp = Qg + base + (size_t)q0 * DH;
        const int lr = tid >> 4;          // 0..15
        const int lc = (tid & 15) << 2;
        #pragma unroll
        for (int i = 0; i < 8; ++i) {
            int r = lr + i * 16;
            float4 v = *(const float4*)(Qp + r * DH + lc);
            v.x *= qscale; v.y *= qscale; v.z *= qscale; v.w *= qscale;
            *(uint2*)&Qs[r * KSTR + lc] = make_uint2(cvt2h(v.x, v.y), cvt2h(v.z, v.w));
        }
    }
    __syncthreads();

    uint32_t qf[2][4][4];
    {
        const __half* Qs = (const __half*)(sm + OFF_Q);
        const int tg = lane & 3;
        #pragma unroll
        for (int mb = 0; mb < 2; ++mb) {
            const int r = R0 + mb * 16 + g;
            #pragma unroll
            for (int kb = 0; kb < 4; ++kb) {
                int d = kb * 16 + tg * 2;
                qf[mb][kb][0] = *(const uint32_t*)&Qs[r * KSTR + d];
                qf[mb][kb][1] = *(const uint32_t*)&Qs[(r + 8) * KSTR + d];
                qf[mb][kb][2] = *(const uint32_t*)&Qs[r * KSTR + d + 8];
                qf[mb][kb][3] = *(const uint32_t*)&Qs[(r + 8) * KSTR + d + 8];
            }
        }
    }

    float oc[2][8][4];
    #pragma unroll
    for (int mb = 0; mb < 2; ++mb)
        #pragma unroll
        for (int n = 0; n < 8; ++n)
            #pragma unroll
            for (int e = 0; e < 4; ++e) oc[mb][n][e] = 0.0f;
    float oce[2][4];
    #pragma unroll
    for (int mb = 0; mb < 2; ++mb)
        #pragma unroll
        for (int e = 0; e < 4; ++e) oce[mb][e] = 0.0f;

    const int krow_off = (lane & 7) + ((lane >> 4) << 3);
    const int kcol_off = ((lane >> 3) & 1) << 3;
    const int vrow_off = (lane & 7) + (((lane >> 3) & 1) << 3);
    const int vcol_off = (lane >> 4) << 3;

    for (int t = 0; t < NT; ++t) {
        const uint32_t kbuf = sbase + OFF_K0 + (t & 1) * 2 * TILE_B;
        const uint32_t vbuf = kbuf + TILE_B;

        CP_WAIT0();
        BARH(1 + half);       // sync only this half's 4 warps; halves drift freely

        if (t + 1 < NT) {
            const uint32_t kn = sbase + OFF_K0 + ((t + 1) & 1) * 2 * TILE_B;
            const __half* kp = gK + (size_t)(t + 1) * BK * DH;
            const __half* vp = gV + (size_t)(t + 1) * BK * DH;
            #pragma unroll
            for (int i = 0; i < 4; ++i) {
                int r = s_row + i * 16;
                uint32_t so = r * ROWB + c_so;
                CP16(kn + so, kp + r * DH + c_col);
                CP16(kn + TILE_B + so, vp + r * DH + c_col);
            }
            CP_COMMIT();
        }

        // ---- S = Q K^T : 32 rows x 64 cols, f16 accumulators ----
        // software pipeline: preload kf for jp+1 before mma(jp)
        uint32_t sch[2][8][2];
        #pragma unroll
        for (int mb = 0; mb < 2; ++mb)
            #pragma unroll
            for (int n = 0; n < 8; ++n) { sch[mb][n][0] = 0u; sch[mb][n][1] = 0u; }

        uint32_t kf[2][4][4];
        {
            const int row0 = J0 + krow_off;
            #pragma unroll
            for (int kb = 0; kb < 4; ++kb)
                ldsm_x4(kbuf + row0 * ROWB + (kb * 16 + kcol_off) * 2, kf[0][kb]);
        }
        #pragma unroll
        for (int jp = 0; jp < 4; ++jp) {
            const int cur = jp & 1, nxt = cur ^ 1;
            if (jp < 3) {
                const int row = J0 + (jp + 1) * 16 + krow_off;
                #pragma unroll
                for (int kb = 0; kb < 4; ++kb)
                    ldsm_x4(kbuf + row * ROWB + (kb * 16 + kcol_off) * 2, kf[nxt][kb]);
            }
            #pragma unroll
            for (int kb = 0; kb < 4; ++kb) {
                #pragma unroll
                for (int mb = 0; mb < 2; ++mb) {
                    mma16816h(sch[mb][2 * jp],     qf[mb][kb], kf[cur][kb][0], kf[cur][kb][1]);
                    mma16816h(sch[mb][2 * jp + 1], qf[mb][kb], kf[cur][kb][2], kf[cur][kb][3]);
                }
            }
        }

        // ---- PV pipelined at kb granularity: preload vf(kb+1), exp(kb) overlaps
        //      tensor work of kb-1, then PV mma(kb) ----
        uint32_t vf[2][4][4];
        uint32_t eo[2][2];
        {
            const int row0 = J0 + vrow_off;
            #pragma unroll
            for (int dp = 0; dp < 4; ++dp)
                ldsm_x4_t(vbuf + row0 * ROWB + (dp * 16 + vcol_off) * 2, vf[0][dp]);
            ldsm_x2_t(vbuf + row0 * ROWB + 128, eo[0][0], eo[0][1]);
        }
        #pragma unroll
        for (int kb = 0; kb < 4; ++kb) {
            const int cur = kb & 1, nxt = cur ^ 1;
            if (kb < 3) {
                const int row = J0 + (kb + 1) * 16 + vrow_off;
                #pragma unroll
                for (int dp = 0; dp < 4; ++dp)
                    ldsm_x4_t(vbuf + row * ROWB + (dp * 16 + vcol_off) * 2, vf[nxt][dp]);
                ldsm_x2_t(vbuf + row * ROWB + 128, eo[nxt][0], eo[nxt][1]);
            }
            // exp for this kb (MUFU) — issues while tensor pipe drains prior mmas
            uint32_t pa[2][4];
            #pragma unroll
            for (int mb = 0; mb < 2; ++mb) {
                pa[mb][0] = h2ex2(sch[mb][2 * kb][0]);
                pa[mb][1] = h2ex2(sch[mb][2 * kb][1]);
                pa[mb][2] = h2ex2(sch[mb][2 * kb + 1][0]);
                pa[mb][3] = h2ex2(sch[mb][2 * kb + 1][1]);
            }
            #pragma unroll
            for (int dp = 0; dp < 4; ++dp) {
                #pragma unroll
                for (int mb = 0; mb < 2; ++mb) {
                    mma16816(oc[mb][2 * dp],     pa[mb], vf[cur][dp][0], vf[cur][dp][1]);
                    mma16816(oc[mb][2 * dp + 1], pa[mb], vf[cur][dp][2], vf[cur][dp][3]);
                }
            }
            #pragma unroll
            for (int mb = 0; mb < 2; ++mb)
                mma16816(oce[mb], pa[mb], eo[cur][0], eo[cur][1]);
        }
    }

    // rowsums: ones-block col 0 (tg==0 lanes): rows R0+16mb+g, +8
    float rsA[2], rsB[2];
    #pragma unroll
    for (int mb = 0; mb < 2; ++mb) {
        rsA[mb] = __shfl_sync(0xffffffffu, oce[mb][0], lane & 28);
        rsB[mb] = __shfl_sync(0xffffffffu, oce[mb][2], lane & 28);
    }

    __syncthreads();   // both halves done; reuse smem for combine

    float* OS = (float*)(sm + OFF_K0);   // 128 x 64 f32 partials (half 1)
    float* RS = (float*)(sm + OFF_Q);    // 128 rowsums (half 1)
    const int tg = lane & 3;

    if (half == 1) {
        #pragma unroll
        for (int mb = 0; mb < 2; ++mb) {
            const int r = R0 + mb * 16 + g;
            #pragma unroll
            for (int n = 0; n < 8; ++n) {
                int c = n * 8 + tg * 2;
                *(float2*)&OS[r * 64 + c]       = make_float2(oc[mb][n][0], oc[mb][n][1]);
                *(float2*)&OS[(r + 8) * 64 + c] = make_float2(oc[mb][n][2], oc[mb][n][3]);
            }
            if (tg == 0) { RS[r] = rsA[mb]; RS[r + 8] = rsB[mb]; }
        }
    }
    __syncthreads();

    if (half == 0) {
        #pragma unroll
        for (int mb = 0; mb < 2; ++mb) {
            const int r = R0 + mb * 16 + g;
            float invA = 1.0f / (rsA[mb] + RS[r]);
            float invB = 1.0f / (rsB[mb] + RS[r + 8]);
            float* OpA = Og + base + (size_t)(q0 + r) * DH;
            float* OpB = OpA + 8 * DH;
            #pragma unroll
            for (int n = 0; n < 8; ++n) {
                int c = n * 8 + tg * 2;
                float2 pA = *(const float2*)&OS[r * 64 + c];
                float2 pB = *(const float2*)&OS[(r + 8) * 64 + c];
                *(float2*)(OpA + c) = make_float2((oc[mb][n][0] + pA.x) * invA,
                                                  (oc[mb][n][1] + pA.y) * invA);
                *(float2*)(OpB + c) = make_float2((oc[mb][n][2] + pB.x) * invB,
                                                  (oc[mb][n][3] + pB.y) * invB);
            }
        }
    }
}

extern "C" void kernel_launch(void* const* d_in, const int* in_sizes, int n_in,
                              void* d_out, int out_size)
{
    const float* Q = (const float*)d_in[0];
    const float* K = (const float*)d_in[1];
    const float* V = (const float*)d_in[2];
    float* O = (float*)d_out;

    cudaFuncSetAttribute(sdpa_r16_kernel,
                         cudaFuncAttributeMaxDynamicSharedMemorySize, SMEM_TOTAL);

    cvt_kv_kernel<<<NELEM / (256 * 4), 256>>>(K, V);

    const float qscale = (1.0f / sqrtf((float)S_LEN)) * 1.4426950408889634f;
    dim3 grid(S_LEN / BQ, 2 * 12);
    sdpa_r16_kernel<<<grid, THREADS, SMEM_TOTAL>>>(Q, O, qscale);
}